// round 11
// baseline (speedup 1.0000x reference)
#include <cuda_runtime.h>
#include <cuda_bf16.h>
#include <cstdint>

// Problem constants: B=8, C=512, H=W=56 -> N=3136, E=256
#define BATCH 8
#define CCH   512
#define NSP   3136
#define EMB   256
#define E3    768
#define SPL2  14      // split-K factor for GEMM2 (3136 = 14 * 224)

// ---------------- scratch (__device__ globals; no allocation allowed) -------
__device__ __nv_bfloat16 g_wqkv[E3 * CCH];                       // 768x512
__device__ float         g_bqkv[E3];
__device__ __nv_bfloat16 g_wo[CCH * EMB];                        // 512x256
__device__ __nv_bfloat16 g_xb[(size_t)BATCH * CCH * NSP];        // per b: 512x3136
__device__ __nv_bfloat16 g_qkv[(size_t)BATCH * E3 * NSP];        // per b: 768x3136
__device__ float         g_part[(size_t)BATCH * SPL2 * EMB * EMB]; // split-K partials
__device__ __nv_bfloat16 g_a2[(size_t)BATCH * EMB * EMB];        // per b: 256x256 (kv^T)
__device__ __nv_bfloat16 g_wp[(size_t)BATCH * CCH * EMB];        // per b: W' = wo@a2/N

__device__ __forceinline__ uint32_t sptr(const void* p) {
    return (uint32_t)__cvta_generic_to_shared(p);
}

// ---------------- fused prep: pack weights + convert x ----------------------
// grid.x covers conv work (total4 chunks of float4); blocks also cover pack.
__global__ void prep_all(const float* __restrict__ x, long long total4,
                         const float* __restrict__ wq, const float* __restrict__ wk,
                         const float* __restrict__ wv, const float* __restrict__ bq,
                         const float* __restrict__ bk, const float* __restrict__ bv,
                         const float* __restrict__ wo)
{
    long long i = (long long)blockIdx.x * blockDim.x + threadIdx.x;
    if (i < total4) {
        float4 v = ((const float4*)x)[i];
        ((__nv_bfloat162*)g_xb)[2 * i]     = __floats2bfloat162_rn(v.x, v.y);
        ((__nv_bfloat162*)g_xb)[2 * i + 1] = __floats2bfloat162_rn(v.z, v.w);
    }
    if (i < E3 * CCH) {
        int r = (int)(i / CCH), c = (int)(i % CCH);
        const float* src = (r < EMB) ? wq : (r < 2 * EMB ? wk : wv);
        g_wqkv[i] = __float2bfloat16(src[(r % EMB) * CCH + c]);
    }
    if (i < CCH * EMB) g_wo[i] = __float2bfloat16(wo[i]);
    if (i < E3) {
        const float* bs = (i < EMB) ? bq : (i < 2 * EMB ? bk : bv);
        g_bqkv[i] = bs[i % EMB];
    }
}

// Sum SPL2 fp32 partials -> bf16 a2
__global__ void reduce_a2()
{
    int i = blockIdx.x * blockDim.x + threadIdx.x;
    if (i >= BATCH * EMB * EMB) return;
    int bz = i / (EMB * EMB), r = i % (EMB * EMB);
    const float* p = g_part + (size_t)bz * SPL2 * EMB * EMB + r;
    float s = 0.f;
#pragma unroll
    for (int k = 0; k < SPL2; k++) s += p[(size_t)k * EMB * EMB];
    g_a2[i] = __float2bfloat16(s);
}

// ---------------- bf16 tensor-core GEMM (NT or NN B operand) -----------------
// C[m][n] = alpha * sum_k A[m][k]*B(k,n) (+bias[m]) (+resid)
//   A: MxK row-major (leading dim lda)
//   BNMAJ=false (NT): B is NxK row-major (leading dim ldb)
//   BNMAJ=true  (NN): B is KxN row-major (row stride ldb)
// grid.z = batch * SPLITS; split-K partials written at blockIdx.z * sC.
// Tile BMxBNx32, warps WGM x WGN, m16n8k16, STAGES-deep cp.async pipeline
// in dynamic shared memory. Loop: wait -> sync -> issue loads -> compute.
#define LDSS 40   // A / NT-B smem row stride (32 + 8 pad)

template<int BM, int BN, bool BNMAJ, int STAGES>
constexpr size_t smem_bytes() {
    return (size_t)STAGES * (BM * LDSS + (BNMAJ ? 32 * (BN + 8) : BN * LDSS))
           * sizeof(__nv_bfloat16);
}

template<int BM, int BN, int WGM, int WGN, int STAGES, int SPLITS,
         bool BNMAJ, bool BIAS, bool RES, bool OUTF32>
__global__ __launch_bounds__(WGM * WGN * 32)
void gemm_bf(const __nv_bfloat16* __restrict__ A, const __nv_bfloat16* __restrict__ B,
             void* __restrict__ Cptr, const float* __restrict__ bias,
             const float* __restrict__ resid,
             int M, int N, int K, int lda, int ldb,
             long long sA, long long sB, long long sC, long long sR, float alpha)
{
    constexpr int T    = WGM * WGN * 32;
    constexpr int WM   = BM / WGM;
    constexpr int WN   = BN / WGN;
    constexpr int MI   = WM / 16;
    constexpr int NJ   = WN / 8;
    constexpr int LDBN = BN + 8;                           // NN B smem row stride
    constexpr int ASTG = BM * LDSS;                        // A elems per stage
    constexpr int BSTG = BNMAJ ? 32 * LDBN : BN * LDSS;    // B elems per stage

    extern __shared__ __align__(16) __nv_bfloat16 smem[];
    __nv_bfloat16* Asm = smem;                  // [STAGES][ASTG]
    __nv_bfloat16* Bsm = smem + STAGES * ASTG;  // [STAGES][BSTG]

    const int bz    = blockIdx.z / SPLITS;
    const int split = blockIdx.z % SPLITS;
    A += bz * sA + (long long)split * K;                               // unit k stride
    B += bz * sB + (BNMAJ ? (long long)split * K * ldb : (long long)split * K);
    const int bm = blockIdx.y * BM, bn = blockIdx.x * BN;
    const int tid = threadIdx.x, lane = tid & 31, warp = tid >> 5;
    const int wm = (warp / WGN) * WM, wn = (warp % WGN) * WN;

    float acc[MI][NJ][4];
#pragma unroll
    for (int i = 0; i < MI; i++)
#pragma unroll
        for (int j = 0; j < NJ; j++)
#pragma unroll
            for (int v = 0; v < 4; v++) acc[i][j][v] = 0.f;

    const int KT = K / 32;

#define LOAD_STAGE(ST, K0)                                                          \
    {                                                                               \
        _Pragma("unroll")                                                           \
        for (int p = 0; p < BM * 4 / T; p++) {                                      \
            int r  = (tid >> 2) + p * (T / 4);                                      \
            int ck = (tid & 3) * 8;                                                 \
            int gm = bm + r;                                                        \
            const __nv_bfloat16* src = A + (long long)gm * lda + (K0) + ck;         \
            uint32_t dst = sptr(&Asm[(ST) * ASTG + r * LDSS + ck]);                 \
            int szz = (gm < M) ? 16 : 0;                                            \
            asm volatile("cp.async.cg.shared.global [%0], [%1], 16, %2;\n"          \
                         :: "r"(dst), "l"(src), "r"(szz));                          \
        }                                                                           \
        if (BNMAJ) {                                                                \
            _Pragma("unroll")                                                       \
            for (int p = 0; p < 32 * (BN / 8) / T; p++) {                           \
                int r  = tid / (BN / 8) + p * (T / (BN / 8));                       \
                int cc = (tid % (BN / 8)) * 8;                                      \
                int gn = bn + cc;                                                   \
                const __nv_bfloat16* src = B + (long long)((K0) + r) * ldb + gn;    \
                uint32_t dst = sptr(&Bsm[(ST) * BSTG + r * LDBN + cc]);             \
                int szz = (gn < N) ? 16 : 0;                                        \
                asm volatile("cp.async.cg.shared.global [%0], [%1], 16, %2;\n"      \
                             :: "r"(dst), "l"(src), "r"(szz));                      \
            }                                                                       \
        } else {                                                                    \
            _Pragma("unroll")                                                       \
            for (int p = 0; p < BN * 4 / T; p++) {                                  \
                int r  = (tid >> 2) + p * (T / 4);                                  \
                int ck = (tid & 3) * 8;                                             \
                int gn = bn + r;                                                    \
                const __nv_bfloat16* src = B + (long long)gn * ldb + (K0) + ck;     \
                uint32_t dst = sptr(&Bsm[(ST) * BSTG + r * LDSS + ck]);             \
                int szz = (gn < N) ? 16 : 0;                                        \
                asm volatile("cp.async.cg.shared.global [%0], [%1], 16, %2;\n"      \
                             :: "r"(dst), "l"(src), "r"(szz));                      \
            }                                                                       \
        }                                                                           \
    }

    // prologue: issue STAGES-1 stages
#pragma unroll
    for (int s = 0; s < STAGES - 1; s++) {
        if (s < KT) LOAD_STAGE(s, s * 32);
        asm volatile("cp.async.commit_group;\n");
    }

    for (int kt = 0; kt < KT; kt++) {
        asm volatile("cp.async.wait_group %0;\n" :: "n"(STAGES - 2));
        __syncthreads();

        // issue loads for stage kt+STAGES-1 BEFORE compute
        int nx = kt + STAGES - 1;
        if (nx < KT) { LOAD_STAGE(nx % STAGES, nx * 32); }
        asm volatile("cp.async.commit_group;\n");

        const int st = kt % STAGES;
        const __nv_bfloat16* as = Asm + st * ASTG;
        const __nv_bfloat16* bs = Bsm + st * BSTG;
#pragma unroll
        for (int kk = 0; kk < 2; kk++) {
            uint32_t af[MI][4], bfr[NJ][2];
#pragma unroll
            for (int i = 0; i < MI; i++) {
                int row = wm + i * 16 + (lane & 15);
                int col = kk * 16 + (lane >> 4) * 8;
                uint32_t addr = sptr(&as[row * LDSS + col]);
                asm volatile("ldmatrix.sync.aligned.m8n8.x4.shared.b16 {%0,%1,%2,%3}, [%4];\n"
                             : "=r"(af[i][0]), "=r"(af[i][1]), "=r"(af[i][2]), "=r"(af[i][3])
                             : "r"(addr));
            }
#pragma unroll
            for (int j = 0; j < NJ; j++) {
                if (BNMAJ) {
                    int kb = kk * 16 + (lane & 15);
                    uint32_t addr = sptr(&bs[kb * LDBN + wn + j * 8]);
                    asm volatile("ldmatrix.sync.aligned.m8n8.x2.trans.shared.b16 {%0,%1}, [%2];\n"
                                 : "=r"(bfr[j][0]), "=r"(bfr[j][1]) : "r"(addr));
                } else {
                    int nrow = wn + j * 8 + (lane & 7);
                    int col = kk * 16 + ((lane >> 3) & 1) * 8;
                    uint32_t addr = sptr(&bs[nrow * LDSS + col]);
                    asm volatile("ldmatrix.sync.aligned.m8n8.x2.shared.b16 {%0,%1}, [%2];\n"
                                 : "=r"(bfr[j][0]), "=r"(bfr[j][1]) : "r"(addr));
                }
            }
#pragma unroll
            for (int i = 0; i < MI; i++)
#pragma unroll
                for (int j = 0; j < NJ; j++) {
                    asm volatile(
                        "mma.sync.aligned.m16n8k16.row.col.f32.bf16.bf16.f32 "
                        "{%0,%1,%2,%3}, {%4,%5,%6,%7}, {%8,%9}, {%0,%1,%2,%3};\n"
                        : "+f"(acc[i][j][0]), "+f"(acc[i][j][1]),
                          "+f"(acc[i][j][2]), "+f"(acc[i][j][3])
                        : "r"(af[i][0]), "r"(af[i][1]), "r"(af[i][2]), "r"(af[i][3]),
                          "r"(bfr[j][0]), "r"(bfr[j][1]));
                }
        }
    }
#undef LOAD_STAGE

    // ---- epilogue ----
    float* Cf = (float*)Cptr + (OUTF32 ? blockIdx.z * sC : 0);
    __nv_bfloat16* Cb = (__nv_bfloat16*)Cptr + (OUTF32 ? 0 : blockIdx.z * sC);
    const float* Rp = RES ? (resid + bz * sR) : nullptr;

#pragma unroll
    for (int i = 0; i < MI; i++) {
        int r0 = bm + wm + i * 16 + (lane >> 2);
#pragma unroll
        for (int j = 0; j < NJ; j++) {
            int c0 = bn + wn + j * 8 + (lane & 3) * 2;
#pragma unroll
            for (int h = 0; h < 2; h++) {
                int rr = r0 + h * 8;
                if (rr < M && c0 < N) {
                    float v0 = acc[i][j][2 * h] * alpha;
                    float v1 = acc[i][j][2 * h + 1] * alpha;
                    if (BIAS) { float bb = bias[rr]; v0 += bb; v1 += bb; }
                    long long idx = (long long)rr * N + c0;
                    if (OUTF32) {
                        if (RES) { v0 += Rp[idx]; v1 += Rp[idx + 1]; }
                        Cf[idx] = v0; Cf[idx + 1] = v1;
                    } else {
                        *(__nv_bfloat162*)&Cb[idx] = __floats2bfloat162_rn(v0, v1);
                    }
                }
            }
        }
    }
}

// ---------------- host launch ------------------------------------------------
extern "C" void kernel_launch(void* const* d_in, const int* in_sizes, int n_in,
                              void* d_out, int out_size)
{
    const float* x  = (const float*)d_in[0];
    const float* wq = (const float*)d_in[1];
    const float* bq = (const float*)d_in[2];
    const float* wk = (const float*)d_in[3];
    const float* bk = (const float*)d_in[4];
    const float* wv = (const float*)d_in[5];
    const float* bv = (const float*)d_in[6];
    const float* wo = (const float*)d_in[7];
    const float* bo = (const float*)d_in[8];
    float* out = (float*)d_out;

    __nv_bfloat16 *qkv, *a2, *wp, *wqkvp, *wop, *xb;
    float *bqkvp, *part;
    cudaGetSymbolAddress((void**)&qkv,   g_qkv);
    cudaGetSymbolAddress((void**)&a2,    g_a2);
    cudaGetSymbolAddress((void**)&wp,    g_wp);
    cudaGetSymbolAddress((void**)&wqkvp, g_wqkv);
    cudaGetSymbolAddress((void**)&wop,   g_wo);
    cudaGetSymbolAddress((void**)&bqkvp, g_bqkv);
    cudaGetSymbolAddress((void**)&xb,    g_xb);
    cudaGetSymbolAddress((void**)&part,  g_part);

    const long long sX  = (long long)CCH * NSP;
    const long long sQK = (long long)E3 * NSP;
    const long long sA2 = (long long)EMB * EMB;
    const long long sWP = (long long)CCH * EMB;

    // kernel instantiations + their dynamic smem sizes
    // G1: 128x64 tile, 8 warps of 32x32 (lower regs -> 3 CTAs/SM, 24 warps).
    // G2/WP/G4: proven R9 configs.
    auto kG1 = gemm_bf<128, 64,  4, 2, 4, 1,    true,  true,  false, false>;
    auto kG2 = gemm_bf<128, 128, 2, 4, 3, SPL2, false, false, false, true>;
    auto kWP = gemm_bf<64,  64,  2, 2, 2, 1,    true,  false, false, false>;
    auto kG4 = gemm_bf<128, 128, 2, 4, 4, 1,    true,  true,  true,  true>;
    constexpr size_t smG1 = smem_bytes<128, 64, true, 4>();
    constexpr size_t smG2 = smem_bytes<128, 128, false, 3>();
    constexpr size_t smWP = smem_bytes<64, 64, true, 2>();
    constexpr size_t smG4 = smem_bytes<128, 128, true, 4>();
    cudaFuncSetAttribute(kG1, cudaFuncAttributeMaxDynamicSharedMemorySize, (int)smG1);
    cudaFuncSetAttribute(kG2, cudaFuncAttributeMaxDynamicSharedMemorySize, (int)smG2);
    cudaFuncSetAttribute(kWP, cudaFuncAttributeMaxDynamicSharedMemorySize, (int)smWP);
    cudaFuncSetAttribute(kG4, cudaFuncAttributeMaxDynamicSharedMemorySize, (int)smG4);

    // prep: pack weights + convert x to bf16 (fused, one launch)
    long long total4 = (long long)BATCH * sX / 4;
    prep_all<<<(unsigned)((total4 + 255) / 256), 256>>>(
        x, total4, wq, wk, wv, bq, bk, bv, wo);

    // GEMM1 (NN, 128x64): qkv[e'][n] = wqkv[e'][c] . xb[c][n] + b
    //                     (M=768,N=3136,K=512)
    kG1<<<dim3((NSP + 63) / 64, E3 / 128, BATCH), 256, smG1>>>(
        wqkvp, xb, qkv, bqkvp, nullptr, E3, NSP, CCH, CCH, NSP,
        0, sX, sQK, 0, 1.f);

    // GEMM2 (NT, split-K=14, 128x128): part[s] = V . K^T    (M=256,N=256,K=224/split)
    kG2<<<dim3(EMB / 128, EMB / 128, BATCH * SPL2), 256, smG2>>>(
        qkv + (long long)2 * EMB * NSP, qkv + (long long)EMB * NSP, part,
        nullptr, nullptr, EMB, EMB, NSP / SPL2, NSP, NSP,
        sQK, sQK, sA2, 0, 1.f);
    reduce_a2<<<(BATCH * EMB * EMB + 255) / 256, 256>>>();

    // W' (NN): wp[c][f] = (1/N) * wo[c][e] . a2[e][f]       (M=512,N=256,K=256)
    kWP<<<dim3(EMB / 64, CCH / 64, BATCH), 128, smWP>>>(
        wop, a2, wp, nullptr, nullptr, CCH, EMB, EMB, EMB, EMB,
        0, sA2, sWP, 0, 1.f / (float)NSP);

    // GEMM4 (NN): out[c][n] = wp[c][f] . q[f][n] + bo[c] + x[c][n]
    //             (M=512,N=3136,K=256)
    kG4<<<dim3((NSP + 127) / 128, CCH / 128, BATCH), 256, smG4>>>(
        wp, qkv, out, bo, x, CCH, NSP, EMB, EMB, NSP,
        sWP, sQK, sX, sX, 1.f);
}

// round 14
// speedup vs baseline: 1.1056x; 1.1056x over previous
#include <cuda_runtime.h>
#include <cuda_bf16.h>
#include <cstdint>

// Problem constants: B=8, C=512, H=W=56 -> N=3136, E=256
#define BATCH 8
#define CCH   512
#define NSP   3136
#define EMB   256
#define E3    768
#define SPL2  14      // split-K factor for GEMM2 (3136 = 14 * 224)

// ---------------- scratch (__device__ globals; no allocation allowed) -------
__device__ __nv_bfloat16 g_wqkv[E3 * CCH];                       // 768x512
__device__ float         g_bqkv[E3];
__device__ __nv_bfloat16 g_wo[CCH * EMB];                        // 512x256
__device__ __nv_bfloat16 g_xb[(size_t)BATCH * CCH * NSP];        // per b: 512x3136
__device__ __nv_bfloat16 g_qkv[(size_t)BATCH * E3 * NSP];        // per b: 768x3136
__device__ __nv_bfloat16 g_part[(size_t)BATCH * SPL2 * EMB * EMB]; // bf16 split-K partials
__device__ __nv_bfloat16 g_a2[(size_t)BATCH * EMB * EMB];        // per b: 256x256 (kv^T)
__device__ __nv_bfloat16 g_wp[(size_t)BATCH * CCH * EMB];        // per b: W' = wo@a2/N

__device__ __forceinline__ uint32_t sptr(const void* p) {
    return (uint32_t)__cvta_generic_to_shared(p);
}

// ---------------- fused prep: pack weights + convert x ----------------------
__global__ void prep_all(const float* __restrict__ x, long long total4,
                         const float* __restrict__ wq, const float* __restrict__ wk,
                         const float* __restrict__ wv, const float* __restrict__ bq,
                         const float* __restrict__ bk, const float* __restrict__ bv,
                         const float* __restrict__ wo)
{
    long long i = (long long)blockIdx.x * blockDim.x + threadIdx.x;
    if (i < total4) {
        float4 v = ((const float4*)x)[i];
        ((__nv_bfloat162*)g_xb)[2 * i]     = __floats2bfloat162_rn(v.x, v.y);
        ((__nv_bfloat162*)g_xb)[2 * i + 1] = __floats2bfloat162_rn(v.z, v.w);
    }
    if (i < E3 * CCH) {
        int r = (int)(i / CCH), c = (int)(i % CCH);
        const float* src = (r < EMB) ? wq : (r < 2 * EMB ? wk : wv);
        g_wqkv[i] = __float2bfloat16(src[(r % EMB) * CCH + c]);
    }
    if (i < CCH * EMB) g_wo[i] = __float2bfloat16(wo[i]);
    if (i < E3) {
        const float* bs = (i < EMB) ? bq : (i < 2 * EMB ? bk : bv);
        g_bqkv[i] = bs[i % EMB];
    }
}

// Sum SPL2 bf16 partials (fp32 accum) -> bf16 a2, vectorized x2
__global__ void reduce_a2()
{
    constexpr int HALF = EMB * EMB / 2;
    int i = blockIdx.x * blockDim.x + threadIdx.x;
    if (i >= BATCH * HALF) return;
    int bz = i / HALF, r = i % HALF;
    const __nv_bfloat162* p =
        (const __nv_bfloat162*)g_part + (size_t)bz * SPL2 * HALF + r;
    float sx = 0.f, sy = 0.f;
#pragma unroll
    for (int k = 0; k < SPL2; k++) {
        float2 v = __bfloat1622float2(p[(size_t)k * HALF]);
        sx += v.x; sy += v.y;
    }
    ((__nv_bfloat162*)g_a2)[i] = __floats2bfloat162_rn(sx, sy);
}

// ---------------- bf16 tensor-core GEMM (NT or NN B operand) -----------------
// C[m][n] = alpha * sum_k A[m][k]*B(k,n) (+bias[m]) (+resid)
//   A: MxK row-major (leading dim lda)
//   BNMAJ=false (NT): B is NxK row-major (leading dim ldb)
//   BNMAJ=true  (NN): B is KxN row-major (row stride ldb)
// grid.z = batch * SPLITS; split-K partials written at blockIdx.z * sC
// (bf16 or fp32 per OUTF32). Tile BMxBNx32, warps WGM x WGN, m16n8k16,
// STAGES-deep cp.async pipeline in dynamic smem.
#define LDSS 40   // A / NT-B smem row stride (32 + 8 pad)

template<int BM, int BN, bool BNMAJ, int STAGES>
constexpr size_t smem_bytes() {
    return (size_t)STAGES * (BM * LDSS + (BNMAJ ? 32 * (BN + 8) : BN * LDSS))
           * sizeof(__nv_bfloat16);
}

template<int BM, int BN, int WGM, int WGN, int STAGES, int SPLITS,
         bool BNMAJ, bool BIAS, bool RES, bool OUTF32>
__global__ __launch_bounds__(WGM * WGN * 32)
void gemm_bf(const __nv_bfloat16* __restrict__ A, const __nv_bfloat16* __restrict__ B,
             void* __restrict__ Cptr, const float* __restrict__ bias,
             const float* __restrict__ resid,
             int M, int N, int K, int lda, int ldb,
             long long sA, long long sB, long long sC, long long sR, float alpha)
{
    constexpr int T    = WGM * WGN * 32;
    constexpr int WM   = BM / WGM;
    constexpr int WN   = BN / WGN;
    constexpr int MI   = WM / 16;
    constexpr int NJ   = WN / 8;
    constexpr int LDBN = BN + 8;                           // NN B smem row stride
    constexpr int ASTG = BM * LDSS;                        // A elems per stage
    constexpr int BSTG = BNMAJ ? 32 * LDBN : BN * LDSS;    // B elems per stage

    extern __shared__ __align__(16) __nv_bfloat16 smem[];
    __nv_bfloat16* Asm = smem;                  // [STAGES][ASTG]
    __nv_bfloat16* Bsm = smem + STAGES * ASTG;  // [STAGES][BSTG]

    const int bz    = blockIdx.z / SPLITS;
    const int split = blockIdx.z % SPLITS;
    A += bz * sA + (long long)split * K;                               // unit k stride
    B += bz * sB + (BNMAJ ? (long long)split * K * ldb : (long long)split * K);
    const int bm = blockIdx.y * BM, bn = blockIdx.x * BN;
    const int tid = threadIdx.x, lane = tid & 31, warp = tid >> 5;
    const int wm = (warp / WGN) * WM, wn = (warp % WGN) * WN;

    float acc[MI][NJ][4];
#pragma unroll
    for (int i = 0; i < MI; i++)
#pragma unroll
        for (int j = 0; j < NJ; j++)
#pragma unroll
            for (int v = 0; v < 4; v++) acc[i][j][v] = 0.f;

    const int KT = K / 32;

#define LOAD_STAGE(ST, K0)                                                          \
    {                                                                               \
        _Pragma("unroll")                                                           \
        for (int p = 0; p < BM * 4 / T; p++) {                                      \
            int r  = (tid >> 2) + p * (T / 4);                                      \
            int ck = (tid & 3) * 8;                                                 \
            int gm = bm + r;                                                        \
            const __nv_bfloat16* src = A + (long long)gm * lda + (K0) + ck;         \
            uint32_t dst = sptr(&Asm[(ST) * ASTG + r * LDSS + ck]);                 \
            int szz = (gm < M) ? 16 : 0;                                            \
            asm volatile("cp.async.cg.shared.global [%0], [%1], 16, %2;\n"          \
                         :: "r"(dst), "l"(src), "r"(szz));                          \
        }                                                                           \
        if (BNMAJ) {                                                                \
            _Pragma("unroll")                                                       \
            for (int p = 0; p < 32 * (BN / 8) / T; p++) {                           \
                int r  = tid / (BN / 8) + p * (T / (BN / 8));                       \
                int cc = (tid % (BN / 8)) * 8;                                      \
                int gn = bn + cc;                                                   \
                const __nv_bfloat16* src = B + (long long)((K0) + r) * ldb + gn;    \
                uint32_t dst = sptr(&Bsm[(ST) * BSTG + r * LDBN + cc]);             \
                int szz = (gn < N) ? 16 : 0;                                        \
                asm volatile("cp.async.cg.shared.global [%0], [%1], 16, %2;\n"      \
                             :: "r"(dst), "l"(src), "r"(szz));                      \
            }                                                                       \
        } else {                                                                    \
            _Pragma("unroll")                                                       \
            for (int p = 0; p < BN * 4 / T; p++) {                                  \
                int r  = (tid >> 2) + p * (T / 4);                                  \
                int ck = (tid & 3) * 8;                                             \
                int gn = bn + r;                                                    \
                const __nv_bfloat16* src = B + (long long)gn * ldb + (K0) + ck;     \
                uint32_t dst = sptr(&Bsm[(ST) * BSTG + r * LDSS + ck]);             \
                int szz = (gn < N) ? 16 : 0;                                        \
                asm volatile("cp.async.cg.shared.global [%0], [%1], 16, %2;\n"      \
                             :: "r"(dst), "l"(src), "r"(szz));                      \
            }                                                                       \
        }                                                                           \
    }

    // prologue: issue STAGES-1 stages
#pragma unroll
    for (int s = 0; s < STAGES - 1; s++) {
        if (s < KT) LOAD_STAGE(s, s * 32);
        asm volatile("cp.async.commit_group;\n");
    }

    for (int kt = 0; kt < KT; kt++) {
        asm volatile("cp.async.wait_group %0;\n" :: "n"(STAGES - 2));
        __syncthreads();

        // issue loads for stage kt+STAGES-1 BEFORE compute
        int nx = kt + STAGES - 1;
        if (nx < KT) { LOAD_STAGE(nx % STAGES, nx * 32); }
        asm volatile("cp.async.commit_group;\n");

        const int st = kt % STAGES;
        const __nv_bfloat16* as = Asm + st * ASTG;
        const __nv_bfloat16* bs = Bsm + st * BSTG;
#pragma unroll
        for (int kk = 0; kk < 2; kk++) {
            uint32_t af[MI][4], bfr[NJ][2];
#pragma unroll
            for (int i = 0; i < MI; i++) {
                int row = wm + i * 16 + (lane & 15);
                int col = kk * 16 + (lane >> 4) * 8;
                uint32_t addr = sptr(&as[row * LDSS + col]);
                asm volatile("ldmatrix.sync.aligned.m8n8.x4.shared.b16 {%0,%1,%2,%3}, [%4];\n"
                             : "=r"(af[i][0]), "=r"(af[i][1]), "=r"(af[i][2]), "=r"(af[i][3])
                             : "r"(addr));
            }
#pragma unroll
            for (int j = 0; j < NJ; j++) {
                if (BNMAJ) {
                    int kb = kk * 16 + (lane & 15);
                    uint32_t addr = sptr(&bs[kb * LDBN + wn + j * 8]);
                    asm volatile("ldmatrix.sync.aligned.m8n8.x2.trans.shared.b16 {%0,%1}, [%2];\n"
                                 : "=r"(bfr[j][0]), "=r"(bfr[j][1]) : "r"(addr));
                } else {
                    int nrow = wn + j * 8 + (lane & 7);
                    int col = kk * 16 + ((lane >> 3) & 1) * 8;
                    uint32_t addr = sptr(&bs[nrow * LDSS + col]);
                    asm volatile("ldmatrix.sync.aligned.m8n8.x2.shared.b16 {%0,%1}, [%2];\n"
                                 : "=r"(bfr[j][0]), "=r"(bfr[j][1]) : "r"(addr));
                }
            }
#pragma unroll
            for (int i = 0; i < MI; i++)
#pragma unroll
                for (int j = 0; j < NJ; j++) {
                    asm volatile(
                        "mma.sync.aligned.m16n8k16.row.col.f32.bf16.bf16.f32 "
                        "{%0,%1,%2,%3}, {%4,%5,%6,%7}, {%8,%9}, {%0,%1,%2,%3};\n"
                        : "+f"(acc[i][j][0]), "+f"(acc[i][j][1]),
                          "+f"(acc[i][j][2]), "+f"(acc[i][j][3])
                        : "r"(af[i][0]), "r"(af[i][1]), "r"(af[i][2]), "r"(af[i][3]),
                          "r"(bfr[j][0]), "r"(bfr[j][1]));
                }
        }
    }
#undef LOAD_STAGE

    // ---- epilogue ----
    // split-K partials index by blockIdx.z; normal kernels by batch (bz)
    const long long czoff = (SPLITS > 1 ? (long long)blockIdx.z : (long long)bz) * sC;
    float* Cf = (float*)Cptr + (OUTF32 ? czoff : 0);
    __nv_bfloat16* Cb = (__nv_bfloat16*)Cptr + (OUTF32 ? 0 : czoff);
    const float* Rp = RES ? (resid + bz * sR) : nullptr;

#pragma unroll
    for (int i = 0; i < MI; i++) {
        int r0 = bm + wm + i * 16 + (lane >> 2);
#pragma unroll
        for (int j = 0; j < NJ; j++) {
            int c0 = bn + wn + j * 8 + (lane & 3) * 2;
#pragma unroll
            for (int h = 0; h < 2; h++) {
                int rr = r0 + h * 8;
                if (rr < M && c0 < N) {
                    float v0 = acc[i][j][2 * h] * alpha;
                    float v1 = acc[i][j][2 * h + 1] * alpha;
                    if (BIAS) { float bb = bias[rr]; v0 += bb; v1 += bb; }
                    long long idx = (long long)rr * N + c0;
                    if (OUTF32) {
                        if (RES) { v0 += Rp[idx]; v1 += Rp[idx + 1]; }
                        Cf[idx] = v0; Cf[idx + 1] = v1;
                    } else {
                        *(__nv_bfloat162*)&Cb[idx] = __floats2bfloat162_rn(v0, v1);
                    }
                }
            }
        }
    }
}

// ---------------- host launch ------------------------------------------------
extern "C" void kernel_launch(void* const* d_in, const int* in_sizes, int n_in,
                              void* d_out, int out_size)
{
    const float* x  = (const float*)d_in[0];
    const float* wq = (const float*)d_in[1];
    const float* bq = (const float*)d_in[2];
    const float* wk = (const float*)d_in[3];
    const float* bk = (const float*)d_in[4];
    const float* wv = (const float*)d_in[5];
    const float* bv = (const float*)d_in[6];
    const float* wo = (const float*)d_in[7];
    const float* bo = (const float*)d_in[8];
    float* out = (float*)d_out;

    __nv_bfloat16 *qkv, *a2, *wp, *wqkvp, *wop, *xb, *part;
    float *bqkvp;
    cudaGetSymbolAddress((void**)&qkv,   g_qkv);
    cudaGetSymbolAddress((void**)&a2,    g_a2);
    cudaGetSymbolAddress((void**)&wp,    g_wp);
    cudaGetSymbolAddress((void**)&wqkvp, g_wqkv);
    cudaGetSymbolAddress((void**)&wop,   g_wo);
    cudaGetSymbolAddress((void**)&bqkvp, g_bqkv);
    cudaGetSymbolAddress((void**)&xb,    g_xb);
    cudaGetSymbolAddress((void**)&part,  g_part);

    const long long sX  = (long long)CCH * NSP;
    const long long sQK = (long long)E3 * NSP;
    const long long sA2 = (long long)EMB * EMB;
    const long long sWP = (long long)CCH * EMB;

    // kernel instantiations + their dynamic smem sizes (R9-proven configs;
    // G2 emits bf16 partials)
    auto kG1 = gemm_bf<128, 128, 2, 4, 4, 1,    true,  true,  false, false>;
    auto kG2 = gemm_bf<128, 128, 2, 4, 3, SPL2, false, false, false, false>;
    auto kWP = gemm_bf<64,  64,  2, 2, 2, 1,    true,  false, false, false>;
    auto kG4 = gemm_bf<128, 128, 2, 4, 4, 1,    true,  true,  true,  true>;
    constexpr size_t smG1 = smem_bytes<128, 128, true, 4>();
    constexpr size_t smG2 = smem_bytes<128, 128, false, 3>();
    constexpr size_t smWP = smem_bytes<64, 64, true, 2>();
    constexpr size_t smG4 = smem_bytes<128, 128, true, 4>();
    cudaFuncSetAttribute(kG1, cudaFuncAttributeMaxDynamicSharedMemorySize, (int)smG1);
    cudaFuncSetAttribute(kG2, cudaFuncAttributeMaxDynamicSharedMemorySize, (int)smG2);
    cudaFuncSetAttribute(kWP, cudaFuncAttributeMaxDynamicSharedMemorySize, (int)smWP);
    cudaFuncSetAttribute(kG4, cudaFuncAttributeMaxDynamicSharedMemorySize, (int)smG4);

    // prep: pack weights + convert x to bf16 (fused, one launch)
    long long total4 = (long long)BATCH * sX / 4;
    prep_all<<<(unsigned)((total4 + 255) / 256), 256>>>(
        x, total4, wq, wk, wv, bq, bk, bv, wo);

    // GEMM1 (NN): qkv[e'][n] = wqkv[e'][c] . xb[c][n] + b   (M=768,N=3136,K=512)
    kG1<<<dim3((NSP + 127) / 128, E3 / 128, BATCH), 256, smG1>>>(
        wqkvp, xb, qkv, bqkvp, nullptr, E3, NSP, CCH, CCH, NSP,
        0, sX, sQK, 0, 1.f);

    // GEMM2 (NT, split-K=14, 128x128, bf16 partials): part[s] = V . K^T
    //        (M=256,N=256,K=224/split)
    kG2<<<dim3(EMB / 128, EMB / 128, BATCH * SPL2), 256, smG2>>>(
        qkv + (long long)2 * EMB * NSP, qkv + (long long)EMB * NSP, part,
        nullptr, nullptr, EMB, EMB, NSP / SPL2, NSP, NSP,
        sQK, sQK, sA2, 0, 1.f);
    reduce_a2<<<(BATCH * EMB * EMB / 2 + 255) / 256, 256>>>();

    // W' (NN): wp[c][f] = (1/N) * wo[c][e] . a2[e][f]       (M=512,N=256,K=256)
    kWP<<<dim3(EMB / 64, CCH / 64, BATCH), 128, smWP>>>(
        wop, a2, wp, nullptr, nullptr, CCH, EMB, EMB, EMB, EMB,
        0, sA2, sWP, 0, 1.f / (float)NSP);

    // GEMM4 (NN): out[c][n] = wp[c][f] . q[f][n] + bo[c] + x[c][n]
    //             (M=512,N=3136,K=256)
    kG4<<<dim3((NSP + 127) / 128, CCH / 128, BATCH), 256, smG4>>>(
        wp, qkv, out, bo, x, CCH, NSP, EMB, EMB, NSP,
        sWP, sQK, sX, sX, 1.f);
}